// round 13
// baseline (speedup 1.0000x reference)
#include <cuda_runtime.h>

// Tree DP on deterministic 4-ary heap: L=4096, B=64, C=2.
// msg[b,cs,k] = lse_{cj}( E[b,cj,j] + msg[b,cj,j] + T[k,j,cs,cj] ), j=(k-1)>>2.
//
// FINAL (measured optimum across 12 rounds): warp-autonomous, zero barriers,
// zero smem. Each WARP owns (subtree r in [21,85), TWO batches bA,bB): T lines
// + index math amortized over 2 batches (2048 warps), and the two batches'
// lse2 chains interleave for ILP across the serial MUFU exp->log. Parent
// locals propagate via shfl. All loads statically indexed, issued up front
// (one DRAM wave, max MLP). Sweep results: NB=1 6.56us, NB=2 6.40us (this),
// NB=4 7.10us (parallelism starved).

#define LN  4096
#define CLN 8192

__device__ __forceinline__ float lse2(float a, float b) {
    float mx = fmaxf(a, b);
    float mn = fminf(a, b);
    return mx + __logf(1.0f + __expf(mn - mx));
}

__global__ void __launch_bounds__(256, 1)
k_all(const float* __restrict__ E, const float* __restrict__ T, float* __restrict__ M)
{
    const int lane = threadIdx.x & 31;
    const int w    = threadIdx.x >> 5;
    const int r    = 21 + blockIdx.x;               // subtree root, [21,85)
    const int bA   = (blockIdx.y * 8 + w) * 2;      // batches bA, bA+1
    const int bB   = bA + 1;

    const int p2 = (r - 1) >> 2;
    const int p1 = (p2 - 1) >> 2;

    const float4* __restrict__ T4 = (const float4*)T;
    const float*  __restrict__ EA = E + bA * CLN;
    const float*  __restrict__ EB = E + bB * CLN;
    float* __restrict__ MA = M + bA * CLN;
    float* __restrict__ MB = M + bB * CLN;

    // ---------------- prefetch (static indices, one DRAM wave) --------------
    float4 tA = __ldg(T4 + p1 * LN + 0);
    float4 tB = __ldg(T4 + p2 * LN + p1);
    float4 tC = __ldg(T4 + r  * LN + p2);

    float aR0 = EA[0],  aR1 = EA[LN],      bR0 = EB[0],  bR1 = EB[LN];
    float a10 = EA[p1], a11 = EA[LN + p1], b10 = EB[p1], b11 = EB[LN + p1];
    float a20 = EA[p2], a21 = EA[LN + p2], b20 = EB[p2], b21 = EB[LN + p2];
    float ar0 = EA[r],  ar1 = EA[LN + r],  br0 = EB[r],  br1 = EB[LN + r];

    // level 3: node n3 = lane&3 (shfl sources: lanes 0-3)
    const int n3 = lane & 3;
    const int k3 = 4 * r + 1 + n3;
    float4 t3 = __ldg(T4 + k3 * LN + r);
    float a30 = 0.f, a31 = 0.f, b30 = 0.f, b31 = 0.f;
    if (lane < 4) {
        a30 = EA[k3];  a31 = EA[LN + k3];
        b30 = EB[k3];  b31 = EB[LN + k3];
    }

    // level 4: node n4 = lane&15 (shfl sources: lanes 0-15)
    const int n4 = lane & 15;
    const int k4 = 16 * r + 5 + n4;
    float4 t4 = __ldg(T4 + k4 * LN + ((k4 - 1) >> 2));
    float a40 = 0.f, a41 = 0.f, b40 = 0.f, b41 = 0.f;
    if (lane < 16) {
        a40 = EA[k4];  a41 = EA[LN + k4];
        b40 = EB[k4];  b41 = EB[LN + k4];
    }

    // level 5 (leaves, no E needed): nodes lane and lane+32
    const int k5a = 64 * r + 21 + lane;
    const int k5b = k5a + 32;
    const bool va = (k5a < LN), vb = (k5b < LN);
    float4 t5a, t5b;
    if (va) t5a = __ldg(T4 + k5a * LN + ((k5a - 1) >> 2));
    if (vb) t5b = __ldg(T4 + k5b * LN + ((k5b - 1) >> 2));

    // node 0 never receives a message -> zero (output poisoned); single writer group
    if (blockIdx.x == 0 && lane < 2) {
        MA[lane * LN] = 0.0f;
        MB[lane * LN] = 0.0f;
    }

    // ---------------- path root -> p1 -> p2 -> r (all lanes; 2 batches) -----
    float ma0 = lse2(aR0 + tA.x, aR1 + tA.y);
    float mb0 = lse2(bR0 + tA.x, bR1 + tA.y);
    float ma1 = lse2(aR0 + tA.z, aR1 + tA.w);
    float mb1 = lse2(bR0 + tA.z, bR1 + tA.w);
    if (lane == 0) {
        MA[p1] = ma0;  MA[LN + p1] = ma1;
        MB[p1] = mb0;  MB[LN + p1] = mb1;
    }
    float la0 = a10 + ma0, la1 = a11 + ma1;
    float lb0 = b10 + mb0, lb1 = b11 + mb1;

    ma0 = lse2(la0 + tB.x, la1 + tB.y);
    mb0 = lse2(lb0 + tB.x, lb1 + tB.y);
    ma1 = lse2(la0 + tB.z, la1 + tB.w);
    mb1 = lse2(lb0 + tB.z, lb1 + tB.w);
    if (lane == 0) {
        MA[p2] = ma0;  MA[LN + p2] = ma1;
        MB[p2] = mb0;  MB[LN + p2] = mb1;
    }
    la0 = a20 + ma0;  la1 = a21 + ma1;
    lb0 = b20 + mb0;  lb1 = b21 + mb1;

    ma0 = lse2(la0 + tC.x, la1 + tC.y);
    mb0 = lse2(lb0 + tC.x, lb1 + tC.y);
    ma1 = lse2(la0 + tC.z, la1 + tC.w);
    mb1 = lse2(lb0 + tC.z, lb1 + tC.w);
    if (lane == 0) {
        MA[r] = ma0;   MA[LN + r] = ma1;
        MB[r] = mb0;   MB[LN + r] = mb1;
    }
    const float lrA0 = ar0 + ma0, lrA1 = ar1 + ma1;
    const float lrB0 = br0 + mb0, lrB1 = br1 + mb1;

    // ---------------- level 3 (4 nodes; lane holds node lane&3) -------------
    float mA30 = lse2(lrA0 + t3.x, lrA1 + t3.y);
    float mB30 = lse2(lrB0 + t3.x, lrB1 + t3.y);
    float mA31 = lse2(lrA0 + t3.z, lrA1 + t3.w);
    float mB31 = lse2(lrB0 + t3.z, lrB1 + t3.w);
    if (lane < 4) {
        MA[k3] = mA30;  MA[LN + k3] = mA31;
        MB[k3] = mB30;  MB[LN + k3] = mB31;
    }
    float lA30 = a30 + mA30, lA31 = a31 + mA31;
    float lB30 = b30 + mB30, lB31 = b31 + mB31;

    // ---------------- level 4 (16 nodes; lane holds node lane&15) -----------
    const int s4 = n4 >> 2;
    float pA0 = __shfl_sync(0xffffffffu, lA30, s4);
    float pA1 = __shfl_sync(0xffffffffu, lA31, s4);
    float pB0 = __shfl_sync(0xffffffffu, lB30, s4);
    float pB1 = __shfl_sync(0xffffffffu, lB31, s4);
    float mA40 = lse2(pA0 + t4.x, pA1 + t4.y);
    float mB40 = lse2(pB0 + t4.x, pB1 + t4.y);
    float mA41 = lse2(pA0 + t4.z, pA1 + t4.w);
    float mB41 = lse2(pB0 + t4.z, pB1 + t4.w);
    if (lane < 16) {
        MA[k4] = mA40;  MA[LN + k4] = mA41;
        MB[k4] = mB40;  MB[LN + k4] = mB41;
    }
    float lA40 = a40 + mA40, lA41 = a41 + mA41;
    float lB40 = b40 + mB40, lB41 = b41 + mB41;

    // ---------------- level 5 (up to 64 leaves) ------------------------------
    const int s5a = lane >> 2;
    const int s5b = 8 + (lane >> 2);
    float xA0 = __shfl_sync(0xffffffffu, lA40, s5a);
    float xA1 = __shfl_sync(0xffffffffu, lA41, s5a);
    float xB0 = __shfl_sync(0xffffffffu, lB40, s5a);
    float xB1 = __shfl_sync(0xffffffffu, lB41, s5a);
    float yA0 = __shfl_sync(0xffffffffu, lA40, s5b);
    float yA1 = __shfl_sync(0xffffffffu, lA41, s5b);
    float yB0 = __shfl_sync(0xffffffffu, lB40, s5b);
    float yB1 = __shfl_sync(0xffffffffu, lB41, s5b);
    if (va) {
        float u0 = lse2(xA0 + t5a.x, xA1 + t5a.y);
        float v0 = lse2(xB0 + t5a.x, xB1 + t5a.y);
        float u1 = lse2(xA0 + t5a.z, xA1 + t5a.w);
        float v1 = lse2(xB0 + t5a.z, xB1 + t5a.w);
        MA[k5a] = u0;  MA[LN + k5a] = u1;       // coalesced
        MB[k5a] = v0;  MB[LN + k5a] = v1;
    }
    if (vb) {
        float u0 = lse2(yA0 + t5b.x, yA1 + t5b.y);
        float v0 = lse2(yB0 + t5b.x, yB1 + t5b.y);
        float u1 = lse2(yA0 + t5b.z, yA1 + t5b.w);
        float v1 = lse2(yB0 + t5b.z, yB1 + t5b.w);
        MA[k5b] = u0;  MA[LN + k5b] = u1;
        MB[k5b] = v0;  MB[LN + k5b] = v1;
    }
}

extern "C" void kernel_launch(void* const* d_in, const int* in_sizes, int n_in,
                              void* d_out, int out_size) {
    const float* E = (const float*)d_in[0];   // emissions   [B, C, L] f32
    const float* T = (const float*)d_in[1];   // transitions [L, L, C, C] f32
    float* M = (float*)d_out;                 // messages    [B, C, L] f32

    dim3 grid(64, 4);                         // 64 subtrees x 4 groups of 8x2 batches
    k_all<<<grid, 256>>>(E, T, M);
}

// round 15
// speedup vs baseline: 1.2798x; 1.2798x over previous
#include <cuda_runtime.h>

// Tree DP on deterministic 4-ary heap: L=4096, B=64, C=2.
// msg[b,cs,k] = lse_{cj}( E[b,cj,j] + msg[b,cj,j] + T[k,j,cs,cj] ), j=(k-1)>>2.
//
// FINAL converged design (best measured: 6.40us kernel / 6.66us wall, R11).
// Warp-autonomous, zero barriers, zero smem. Each WARP owns (subtree r in
// [21,85), TWO batches bA,bB): T lines + index math amortized over 2 batches
// (2048 warps), two batches' lse2 chains interleaved for ILP over the serial
// MUFU exp->log. Parent locals propagate via shfl. All loads statically
// indexed, issued up front (one DRAM wave, max MLP).
// Sweep: NB=1 6.56us, NB=2 6.40us (this), NB=4 7.10us. Remaining variance is
// environment clock drift (identical binary measured 6.40 and 7.14).

#define LN  4096
#define CLN 8192

__device__ __forceinline__ float lse2(float a, float b) {
    float mx = fmaxf(a, b);
    float mn = fminf(a, b);
    return mx + __logf(1.0f + __expf(mn - mx));
}

__global__ void __launch_bounds__(256, 1)
k_all(const float* __restrict__ E, const float* __restrict__ T, float* __restrict__ M)
{
    const int lane = threadIdx.x & 31;
    const int w    = threadIdx.x >> 5;
    const int r    = 21 + blockIdx.x;               // subtree root, [21,85)
    const int bA   = (blockIdx.y * 8 + w) * 2;      // batches bA, bA+1
    const int bB   = bA + 1;

    const int p2 = (r - 1) >> 2;
    const int p1 = (p2 - 1) >> 2;

    const float4* __restrict__ T4 = (const float4*)T;
    const float*  __restrict__ EA = E + bA * CLN;
    const float*  __restrict__ EB = E + bB * CLN;
    float* __restrict__ MA = M + bA * CLN;
    float* __restrict__ MB = M + bB * CLN;

    // ---------------- prefetch (static indices, one DRAM wave) --------------
    float4 tA = __ldg(T4 + p1 * LN + 0);
    float4 tB = __ldg(T4 + p2 * LN + p1);
    float4 tC = __ldg(T4 + r  * LN + p2);

    float aR0 = EA[0],  aR1 = EA[LN],      bR0 = EB[0],  bR1 = EB[LN];
    float a10 = EA[p1], a11 = EA[LN + p1], b10 = EB[p1], b11 = EB[LN + p1];
    float a20 = EA[p2], a21 = EA[LN + p2], b20 = EB[p2], b21 = EB[LN + p2];
    float ar0 = EA[r],  ar1 = EA[LN + r],  br0 = EB[r],  br1 = EB[LN + r];

    // level 3: node n3 = lane&3 (shfl sources: lanes 0-3)
    const int n3 = lane & 3;
    const int k3 = 4 * r + 1 + n3;
    float4 t3 = __ldg(T4 + k3 * LN + r);
    float a30 = 0.f, a31 = 0.f, b30 = 0.f, b31 = 0.f;
    if (lane < 4) {
        a30 = EA[k3];  a31 = EA[LN + k3];
        b30 = EB[k3];  b31 = EB[LN + k3];
    }

    // level 4: node n4 = lane&15 (shfl sources: lanes 0-15)
    const int n4 = lane & 15;
    const int k4 = 16 * r + 5 + n4;
    float4 t4 = __ldg(T4 + k4 * LN + ((k4 - 1) >> 2));
    float a40 = 0.f, a41 = 0.f, b40 = 0.f, b41 = 0.f;
    if (lane < 16) {
        a40 = EA[k4];  a41 = EA[LN + k4];
        b40 = EB[k4];  b41 = EB[LN + k4];
    }

    // level 5 (leaves, no E needed): nodes lane and lane+32
    const int k5a = 64 * r + 21 + lane;
    const int k5b = k5a + 32;
    const bool va = (k5a < LN), vb = (k5b < LN);
    float4 t5a, t5b;
    if (va) t5a = __ldg(T4 + k5a * LN + ((k5a - 1) >> 2));
    if (vb) t5b = __ldg(T4 + k5b * LN + ((k5b - 1) >> 2));

    // node 0 never receives a message -> zero (output poisoned); single writer group
    if (blockIdx.x == 0 && lane < 2) {
        MA[lane * LN] = 0.0f;
        MB[lane * LN] = 0.0f;
    }

    // ---------------- path root -> p1 -> p2 -> r (all lanes; 2 batches) -----
    float ma0 = lse2(aR0 + tA.x, aR1 + tA.y);
    float mb0 = lse2(bR0 + tA.x, bR1 + tA.y);
    float ma1 = lse2(aR0 + tA.z, aR1 + tA.w);
    float mb1 = lse2(bR0 + tA.z, bR1 + tA.w);
    if (lane == 0) {
        MA[p1] = ma0;  MA[LN + p1] = ma1;
        MB[p1] = mb0;  MB[LN + p1] = mb1;
    }
    float la0 = a10 + ma0, la1 = a11 + ma1;
    float lb0 = b10 + mb0, lb1 = b11 + mb1;

    ma0 = lse2(la0 + tB.x, la1 + tB.y);
    mb0 = lse2(lb0 + tB.x, lb1 + tB.y);
    ma1 = lse2(la0 + tB.z, la1 + tB.w);
    mb1 = lse2(lb0 + tB.z, lb1 + tB.w);
    if (lane == 0) {
        MA[p2] = ma0;  MA[LN + p2] = ma1;
        MB[p2] = mb0;  MB[LN + p2] = mb1;
    }
    la0 = a20 + ma0;  la1 = a21 + ma1;
    lb0 = b20 + mb0;  lb1 = b21 + mb1;

    ma0 = lse2(la0 + tC.x, la1 + tC.y);
    mb0 = lse2(lb0 + tC.x, lb1 + tC.y);
    ma1 = lse2(la0 + tC.z, la1 + tC.w);
    mb1 = lse2(lb0 + tC.z, lb1 + tC.w);
    if (lane == 0) {
        MA[r] = ma0;   MA[LN + r] = ma1;
        MB[r] = mb0;   MB[LN + r] = mb1;
    }
    const float lrA0 = ar0 + ma0, lrA1 = ar1 + ma1;
    const float lrB0 = br0 + mb0, lrB1 = br1 + mb1;

    // ---------------- level 3 (4 nodes; lane holds node lane&3) -------------
    float mA30 = lse2(lrA0 + t3.x, lrA1 + t3.y);
    float mB30 = lse2(lrB0 + t3.x, lrB1 + t3.y);
    float mA31 = lse2(lrA0 + t3.z, lrA1 + t3.w);
    float mB31 = lse2(lrB0 + t3.z, lrB1 + t3.w);
    if (lane < 4) {
        MA[k3] = mA30;  MA[LN + k3] = mA31;
        MB[k3] = mB30;  MB[LN + k3] = mB31;
    }
    float lA30 = a30 + mA30, lA31 = a31 + mA31;
    float lB30 = b30 + mB30, lB31 = b31 + mB31;

    // ---------------- level 4 (16 nodes; lane holds node lane&15) -----------
    const int s4 = n4 >> 2;
    float pA0 = __shfl_sync(0xffffffffu, lA30, s4);
    float pA1 = __shfl_sync(0xffffffffu, lA31, s4);
    float pB0 = __shfl_sync(0xffffffffu, lB30, s4);
    float pB1 = __shfl_sync(0xffffffffu, lB31, s4);
    float mA40 = lse2(pA0 + t4.x, pA1 + t4.y);
    float mB40 = lse2(pB0 + t4.x, pB1 + t4.y);
    float mA41 = lse2(pA0 + t4.z, pA1 + t4.w);
    float mB41 = lse2(pB0 + t4.z, pB1 + t4.w);
    if (lane < 16) {
        MA[k4] = mA40;  MA[LN + k4] = mA41;
        MB[k4] = mB40;  MB[LN + k4] = mB41;
    }
    float lA40 = a40 + mA40, lA41 = a41 + mA41;
    float lB40 = b40 + mB40, lB41 = b41 + mB41;

    // ---------------- level 5 (up to 64 leaves) ------------------------------
    const int s5a = lane >> 2;
    const int s5b = 8 + (lane >> 2);
    float xA0 = __shfl_sync(0xffffffffu, lA40, s5a);
    float xA1 = __shfl_sync(0xffffffffu, lA41, s5a);
    float xB0 = __shfl_sync(0xffffffffu, lB40, s5a);
    float xB1 = __shfl_sync(0xffffffffu, lB41, s5a);
    float yA0 = __shfl_sync(0xffffffffu, lA40, s5b);
    float yA1 = __shfl_sync(0xffffffffu, lA41, s5b);
    float yB0 = __shfl_sync(0xffffffffu, lB40, s5b);
    float yB1 = __shfl_sync(0xffffffffu, lB41, s5b);
    if (va) {
        float u0 = lse2(xA0 + t5a.x, xA1 + t5a.y);
        float v0 = lse2(xB0 + t5a.x, xB1 + t5a.y);
        float u1 = lse2(xA0 + t5a.z, xA1 + t5a.w);
        float v1 = lse2(xB0 + t5a.z, xB1 + t5a.w);
        MA[k5a] = u0;  MA[LN + k5a] = u1;       // coalesced
        MB[k5a] = v0;  MB[LN + k5a] = v1;
    }
    if (vb) {
        float u0 = lse2(yA0 + t5b.x, yA1 + t5b.y);
        float v0 = lse2(yB0 + t5b.x, yB1 + t5b.y);
        float u1 = lse2(yA0 + t5b.z, yA1 + t5b.w);
        float v1 = lse2(yB0 + t5b.z, yB1 + t5b.w);
        MA[k5b] = u0;  MA[LN + k5b] = u1;
        MB[k5b] = v0;  MB[LN + k5b] = v1;
    }
}

extern "C" void kernel_launch(void* const* d_in, const int* in_sizes, int n_in,
                              void* d_out, int out_size) {
    const float* E = (const float*)d_in[0];   // emissions   [B, C, L] f32
    const float* T = (const float*)d_in[1];   // transitions [L, L, C, C] f32
    float* M = (float*)d_out;                 // messages    [B, C, L] f32

    dim3 grid(64, 4);                         // 64 subtrees x 4 groups of 8x2 batches
    k_all<<<grid, 256>>>(E, T, M);
}

// round 16
// speedup vs baseline: 1.3413x; 1.0481x over previous
#include <cuda_runtime.h>

// Tree DP on deterministic 4-ary heap: L=4096, B=64, C=2.
// msg[b,cs,k] = lse_{cj}( E[b,cj,j] + msg[b,cj,j] + T[k,j,cs,cj] ), j=(k-1)>>2.
//
// FINAL converged design (best measured: 6.40us kernel / 6.66us wall, R11;
// identical binary re-measured 7.14 and 6.72 -> environment noise band).
// Warp-autonomous, zero barriers, zero smem. Each WARP owns (subtree r in
// [21,85), TWO batches bA,bB): T lines + index math amortized over 2 batches
// (2048 warps), two batches' lse2 chains interleaved for ILP over the serial
// MUFU exp->log. Parent locals propagate via shfl. All loads statically
// indexed, issued up front (one DRAM wave, max MLP).
// Sweep: NB=1 6.56us, NB=2 6.40us (this), NB=4 7.10us.

#define LN  4096
#define CLN 8192

__device__ __forceinline__ float lse2(float a, float b) {
    float mx = fmaxf(a, b);
    float mn = fminf(a, b);
    return mx + __logf(1.0f + __expf(mn - mx));
}

__global__ void __launch_bounds__(256, 1)
k_all(const float* __restrict__ E, const float* __restrict__ T, float* __restrict__ M)
{
    const int lane = threadIdx.x & 31;
    const int w    = threadIdx.x >> 5;
    const int r    = 21 + blockIdx.x;               // subtree root, [21,85)
    const int bA   = (blockIdx.y * 8 + w) * 2;      // batches bA, bA+1
    const int bB   = bA + 1;

    const int p2 = (r - 1) >> 2;
    const int p1 = (p2 - 1) >> 2;

    const float4* __restrict__ T4 = (const float4*)T;
    const float*  __restrict__ EA = E + bA * CLN;
    const float*  __restrict__ EB = E + bB * CLN;
    float* __restrict__ MA = M + bA * CLN;
    float* __restrict__ MB = M + bB * CLN;

    // ---------------- prefetch (static indices, one DRAM wave) --------------
    float4 tA = __ldg(T4 + p1 * LN + 0);
    float4 tB = __ldg(T4 + p2 * LN + p1);
    float4 tC = __ldg(T4 + r  * LN + p2);

    float aR0 = EA[0],  aR1 = EA[LN],      bR0 = EB[0],  bR1 = EB[LN];
    float a10 = EA[p1], a11 = EA[LN + p1], b10 = EB[p1], b11 = EB[LN + p1];
    float a20 = EA[p2], a21 = EA[LN + p2], b20 = EB[p2], b21 = EB[LN + p2];
    float ar0 = EA[r],  ar1 = EA[LN + r],  br0 = EB[r],  br1 = EB[LN + r];

    // level 3: node n3 = lane&3 (shfl sources: lanes 0-3)
    const int n3 = lane & 3;
    const int k3 = 4 * r + 1 + n3;
    float4 t3 = __ldg(T4 + k3 * LN + r);
    float a30 = 0.f, a31 = 0.f, b30 = 0.f, b31 = 0.f;
    if (lane < 4) {
        a30 = EA[k3];  a31 = EA[LN + k3];
        b30 = EB[k3];  b31 = EB[LN + k3];
    }

    // level 4: node n4 = lane&15 (shfl sources: lanes 0-15)
    const int n4 = lane & 15;
    const int k4 = 16 * r + 5 + n4;
    float4 t4 = __ldg(T4 + k4 * LN + ((k4 - 1) >> 2));
    float a40 = 0.f, a41 = 0.f, b40 = 0.f, b41 = 0.f;
    if (lane < 16) {
        a40 = EA[k4];  a41 = EA[LN + k4];
        b40 = EB[k4];  b41 = EB[LN + k4];
    }

    // level 5 (leaves, no E needed): nodes lane and lane+32
    const int k5a = 64 * r + 21 + lane;
    const int k5b = k5a + 32;
    const bool va = (k5a < LN), vb = (k5b < LN);
    float4 t5a, t5b;
    if (va) t5a = __ldg(T4 + k5a * LN + ((k5a - 1) >> 2));
    if (vb) t5b = __ldg(T4 + k5b * LN + ((k5b - 1) >> 2));

    // node 0 never receives a message -> zero (output poisoned); single writer group
    if (blockIdx.x == 0 && lane < 2) {
        MA[lane * LN] = 0.0f;
        MB[lane * LN] = 0.0f;
    }

    // ---------------- path root -> p1 -> p2 -> r (all lanes; 2 batches) -----
    float ma0 = lse2(aR0 + tA.x, aR1 + tA.y);
    float mb0 = lse2(bR0 + tA.x, bR1 + tA.y);
    float ma1 = lse2(aR0 + tA.z, aR1 + tA.w);
    float mb1 = lse2(bR0 + tA.z, bR1 + tA.w);
    if (lane == 0) {
        MA[p1] = ma0;  MA[LN + p1] = ma1;
        MB[p1] = mb0;  MB[LN + p1] = mb1;
    }
    float la0 = a10 + ma0, la1 = a11 + ma1;
    float lb0 = b10 + mb0, lb1 = b11 + mb1;

    ma0 = lse2(la0 + tB.x, la1 + tB.y);
    mb0 = lse2(lb0 + tB.x, lb1 + tB.y);
    ma1 = lse2(la0 + tB.z, la1 + tB.w);
    mb1 = lse2(lb0 + tB.z, lb1 + tB.w);
    if (lane == 0) {
        MA[p2] = ma0;  MA[LN + p2] = ma1;
        MB[p2] = mb0;  MB[LN + p2] = mb1;
    }
    la0 = a20 + ma0;  la1 = a21 + ma1;
    lb0 = b20 + mb0;  lb1 = b21 + mb1;

    ma0 = lse2(la0 + tC.x, la1 + tC.y);
    mb0 = lse2(lb0 + tC.x, lb1 + tC.y);
    ma1 = lse2(la0 + tC.z, la1 + tC.w);
    mb1 = lse2(lb0 + tC.z, lb1 + tC.w);
    if (lane == 0) {
        MA[r] = ma0;   MA[LN + r] = ma1;
        MB[r] = mb0;   MB[LN + r] = mb1;
    }
    const float lrA0 = ar0 + ma0, lrA1 = ar1 + ma1;
    const float lrB0 = br0 + mb0, lrB1 = br1 + mb1;

    // ---------------- level 3 (4 nodes; lane holds node lane&3) -------------
    float mA30 = lse2(lrA0 + t3.x, lrA1 + t3.y);
    float mB30 = lse2(lrB0 + t3.x, lrB1 + t3.y);
    float mA31 = lse2(lrA0 + t3.z, lrA1 + t3.w);
    float mB31 = lse2(lrB0 + t3.z, lrB1 + t3.w);
    if (lane < 4) {
        MA[k3] = mA30;  MA[LN + k3] = mA31;
        MB[k3] = mB30;  MB[LN + k3] = mB31;
    }
    float lA30 = a30 + mA30, lA31 = a31 + mA31;
    float lB30 = b30 + mB30, lB31 = b31 + mB31;

    // ---------------- level 4 (16 nodes; lane holds node lane&15) -----------
    const int s4 = n4 >> 2;
    float pA0 = __shfl_sync(0xffffffffu, lA30, s4);
    float pA1 = __shfl_sync(0xffffffffu, lA31, s4);
    float pB0 = __shfl_sync(0xffffffffu, lB30, s4);
    float pB1 = __shfl_sync(0xffffffffu, lB31, s4);
    float mA40 = lse2(pA0 + t4.x, pA1 + t4.y);
    float mB40 = lse2(pB0 + t4.x, pB1 + t4.y);
    float mA41 = lse2(pA0 + t4.z, pA1 + t4.w);
    float mB41 = lse2(pB0 + t4.z, pB1 + t4.w);
    if (lane < 16) {
        MA[k4] = mA40;  MA[LN + k4] = mA41;
        MB[k4] = mB40;  MB[LN + k4] = mB41;
    }
    float lA40 = a40 + mA40, lA41 = a41 + mA41;
    float lB40 = b40 + mB40, lB41 = b41 + mB41;

    // ---------------- level 5 (up to 64 leaves) ------------------------------
    const int s5a = lane >> 2;
    const int s5b = 8 + (lane >> 2);
    float xA0 = __shfl_sync(0xffffffffu, lA40, s5a);
    float xA1 = __shfl_sync(0xffffffffu, lA41, s5a);
    float xB0 = __shfl_sync(0xffffffffu, lB40, s5a);
    float xB1 = __shfl_sync(0xffffffffu, lB41, s5a);
    float yA0 = __shfl_sync(0xffffffffu, lA40, s5b);
    float yA1 = __shfl_sync(0xffffffffu, lA41, s5b);
    float yB0 = __shfl_sync(0xffffffffu, lB40, s5b);
    float yB1 = __shfl_sync(0xffffffffu, lB41, s5b);
    if (va) {
        float u0 = lse2(xA0 + t5a.x, xA1 + t5a.y);
        float v0 = lse2(xB0 + t5a.x, xB1 + t5a.y);
        float u1 = lse2(xA0 + t5a.z, xA1 + t5a.w);
        float v1 = lse2(xB0 + t5a.z, xB1 + t5a.w);
        MA[k5a] = u0;  MA[LN + k5a] = u1;       // coalesced
        MB[k5a] = v0;  MB[LN + k5a] = v1;
    }
    if (vb) {
        float u0 = lse2(yA0 + t5b.x, yA1 + t5b.y);
        float v0 = lse2(yB0 + t5b.x, yB1 + t5b.y);
        float u1 = lse2(yA0 + t5b.z, yA1 + t5b.w);
        float v1 = lse2(yB0 + t5b.z, yB1 + t5b.w);
        MA[k5b] = u0;  MA[LN + k5b] = u1;
        MB[k5b] = v0;  MB[LN + k5b] = v1;
    }
}

extern "C" void kernel_launch(void* const* d_in, const int* in_sizes, int n_in,
                              void* d_out, int out_size) {
    const float* E = (const float*)d_in[0];   // emissions   [B, C, L] f32
    const float* T = (const float*)d_in[1];   // transitions [L, L, C, C] f32
    float* M = (float*)d_out;                 // messages    [B, C, L] f32

    dim3 grid(64, 4);                         // 64 subtrees x 4 groups of 8x2 batches
    k_all<<<grid, 256>>>(E, T, M);
}

// round 17
// speedup vs baseline: 1.3478x; 1.0048x over previous
#include <cuda_runtime.h>

// Tree DP on deterministic 4-ary heap: L=4096, B=64, C=2.
// msg[b,cs,k] = lse_{cj}( E[b,cj,j] + msg[b,cj,j] + T[k,j,cs,cj] ), j=(k-1)>>2.
//
// FINAL converged design. Best measured: 6.40us kernel / 6.66us wall (R11);
// identical binary re-measured 7.14/6.72/6.62 kernel -> environment noise
// band, floor ~6.5us (launch envelope + one DRAM wave + 6-level chain).
// Warp-autonomous, zero barriers, zero smem. Each WARP owns (subtree r in
// [21,85), TWO batches bA,bB): T lines + index math amortized over 2 batches
// (2048 warps), two batches' lse2 chains interleaved for ILP over the serial
// MUFU exp->log. Parent locals propagate via shfl. All loads statically
// indexed, issued up front (one DRAM wave, max MLP).
// Sweep: NB=1 6.56us, NB=2 6.40us (this), NB=4 7.10us.

#define LN  4096
#define CLN 8192

__device__ __forceinline__ float lse2(float a, float b) {
    float mx = fmaxf(a, b);
    float mn = fminf(a, b);
    return mx + __logf(1.0f + __expf(mn - mx));
}

__global__ void __launch_bounds__(256, 1)
k_all(const float* __restrict__ E, const float* __restrict__ T, float* __restrict__ M)
{
    const int lane = threadIdx.x & 31;
    const int w    = threadIdx.x >> 5;
    const int r    = 21 + blockIdx.x;               // subtree root, [21,85)
    const int bA   = (blockIdx.y * 8 + w) * 2;      // batches bA, bA+1
    const int bB   = bA + 1;

    const int p2 = (r - 1) >> 2;
    const int p1 = (p2 - 1) >> 2;

    const float4* __restrict__ T4 = (const float4*)T;
    const float*  __restrict__ EA = E + bA * CLN;
    const float*  __restrict__ EB = E + bB * CLN;
    float* __restrict__ MA = M + bA * CLN;
    float* __restrict__ MB = M + bB * CLN;

    // ---------------- prefetch (static indices, one DRAM wave) --------------
    float4 tA = __ldg(T4 + p1 * LN + 0);
    float4 tB = __ldg(T4 + p2 * LN + p1);
    float4 tC = __ldg(T4 + r  * LN + p2);

    float aR0 = EA[0],  aR1 = EA[LN],      bR0 = EB[0],  bR1 = EB[LN];
    float a10 = EA[p1], a11 = EA[LN + p1], b10 = EB[p1], b11 = EB[LN + p1];
    float a20 = EA[p2], a21 = EA[LN + p2], b20 = EB[p2], b21 = EB[LN + p2];
    float ar0 = EA[r],  ar1 = EA[LN + r],  br0 = EB[r],  br1 = EB[LN + r];

    // level 3: node n3 = lane&3 (shfl sources: lanes 0-3)
    const int n3 = lane & 3;
    const int k3 = 4 * r + 1 + n3;
    float4 t3 = __ldg(T4 + k3 * LN + r);
    float a30 = 0.f, a31 = 0.f, b30 = 0.f, b31 = 0.f;
    if (lane < 4) {
        a30 = EA[k3];  a31 = EA[LN + k3];
        b30 = EB[k3];  b31 = EB[LN + k3];
    }

    // level 4: node n4 = lane&15 (shfl sources: lanes 0-15)
    const int n4 = lane & 15;
    const int k4 = 16 * r + 5 + n4;
    float4 t4 = __ldg(T4 + k4 * LN + ((k4 - 1) >> 2));
    float a40 = 0.f, a41 = 0.f, b40 = 0.f, b41 = 0.f;
    if (lane < 16) {
        a40 = EA[k4];  a41 = EA[LN + k4];
        b40 = EB[k4];  b41 = EB[LN + k4];
    }

    // level 5 (leaves, no E needed): nodes lane and lane+32
    const int k5a = 64 * r + 21 + lane;
    const int k5b = k5a + 32;
    const bool va = (k5a < LN), vb = (k5b < LN);
    float4 t5a, t5b;
    if (va) t5a = __ldg(T4 + k5a * LN + ((k5a - 1) >> 2));
    if (vb) t5b = __ldg(T4 + k5b * LN + ((k5b - 1) >> 2));

    // node 0 never receives a message -> zero (output poisoned); single writer group
    if (blockIdx.x == 0 && lane < 2) {
        MA[lane * LN] = 0.0f;
        MB[lane * LN] = 0.0f;
    }

    // ---------------- path root -> p1 -> p2 -> r (all lanes; 2 batches) -----
    float ma0 = lse2(aR0 + tA.x, aR1 + tA.y);
    float mb0 = lse2(bR0 + tA.x, bR1 + tA.y);
    float ma1 = lse2(aR0 + tA.z, aR1 + tA.w);
    float mb1 = lse2(bR0 + tA.z, bR1 + tA.w);
    if (lane == 0) {
        MA[p1] = ma0;  MA[LN + p1] = ma1;
        MB[p1] = mb0;  MB[LN + p1] = mb1;
    }
    float la0 = a10 + ma0, la1 = a11 + ma1;
    float lb0 = b10 + mb0, lb1 = b11 + mb1;

    ma0 = lse2(la0 + tB.x, la1 + tB.y);
    mb0 = lse2(lb0 + tB.x, lb1 + tB.y);
    ma1 = lse2(la0 + tB.z, la1 + tB.w);
    mb1 = lse2(lb0 + tB.z, lb1 + tB.w);
    if (lane == 0) {
        MA[p2] = ma0;  MA[LN + p2] = ma1;
        MB[p2] = mb0;  MB[LN + p2] = mb1;
    }
    la0 = a20 + ma0;  la1 = a21 + ma1;
    lb0 = b20 + mb0;  lb1 = b21 + mb1;

    ma0 = lse2(la0 + tC.x, la1 + tC.y);
    mb0 = lse2(lb0 + tC.x, lb1 + tC.y);
    ma1 = lse2(la0 + tC.z, la1 + tC.w);
    mb1 = lse2(lb0 + tC.z, lb1 + tC.w);
    if (lane == 0) {
        MA[r] = ma0;   MA[LN + r] = ma1;
        MB[r] = mb0;   MB[LN + r] = mb1;
    }
    const float lrA0 = ar0 + ma0, lrA1 = ar1 + ma1;
    const float lrB0 = br0 + mb0, lrB1 = br1 + mb1;

    // ---------------- level 3 (4 nodes; lane holds node lane&3) -------------
    float mA30 = lse2(lrA0 + t3.x, lrA1 + t3.y);
    float mB30 = lse2(lrB0 + t3.x, lrB1 + t3.y);
    float mA31 = lse2(lrA0 + t3.z, lrA1 + t3.w);
    float mB31 = lse2(lrB0 + t3.z, lrB1 + t3.w);
    if (lane < 4) {
        MA[k3] = mA30;  MA[LN + k3] = mA31;
        MB[k3] = mB30;  MB[LN + k3] = mB31;
    }
    float lA30 = a30 + mA30, lA31 = a31 + mA31;
    float lB30 = b30 + mB30, lB31 = b31 + mB31;

    // ---------------- level 4 (16 nodes; lane holds node lane&15) -----------
    const int s4 = n4 >> 2;
    float pA0 = __shfl_sync(0xffffffffu, lA30, s4);
    float pA1 = __shfl_sync(0xffffffffu, lA31, s4);
    float pB0 = __shfl_sync(0xffffffffu, lB30, s4);
    float pB1 = __shfl_sync(0xffffffffu, lB31, s4);
    float mA40 = lse2(pA0 + t4.x, pA1 + t4.y);
    float mB40 = lse2(pB0 + t4.x, pB1 + t4.y);
    float mA41 = lse2(pA0 + t4.z, pA1 + t4.w);
    float mB41 = lse2(pB0 + t4.z, pB1 + t4.w);
    if (lane < 16) {
        MA[k4] = mA40;  MA[LN + k4] = mA41;
        MB[k4] = mB40;  MB[LN + k4] = mB41;
    }
    float lA40 = a40 + mA40, lA41 = a41 + mA41;
    float lB40 = b40 + mB40, lB41 = b41 + mB41;

    // ---------------- level 5 (up to 64 leaves) ------------------------------
    const int s5a = lane >> 2;
    const int s5b = 8 + (lane >> 2);
    float xA0 = __shfl_sync(0xffffffffu, lA40, s5a);
    float xA1 = __shfl_sync(0xffffffffu, lA41, s5a);
    float xB0 = __shfl_sync(0xffffffffu, lB40, s5a);
    float xB1 = __shfl_sync(0xffffffffu, lB41, s5a);
    float yA0 = __shfl_sync(0xffffffffu, lA40, s5b);
    float yA1 = __shfl_sync(0xffffffffu, lA41, s5b);
    float yB0 = __shfl_sync(0xffffffffu, lB40, s5b);
    float yB1 = __shfl_sync(0xffffffffu, lB41, s5b);
    if (va) {
        float u0 = lse2(xA0 + t5a.x, xA1 + t5a.y);
        float v0 = lse2(xB0 + t5a.x, xB1 + t5a.y);
        float u1 = lse2(xA0 + t5a.z, xA1 + t5a.w);
        float v1 = lse2(xB0 + t5a.z, xB1 + t5a.w);
        MA[k5a] = u0;  MA[LN + k5a] = u1;       // coalesced
        MB[k5a] = v0;  MB[LN + k5a] = v1;
    }
    if (vb) {
        float u0 = lse2(yA0 + t5b.x, yA1 + t5b.y);
        float v0 = lse2(yB0 + t5b.x, yB1 + t5b.y);
        float u1 = lse2(yA0 + t5b.z, yA1 + t5b.w);
        float v1 = lse2(yB0 + t5b.z, yB1 + t5b.w);
        MA[k5b] = u0;  MA[LN + k5b] = u1;
        MB[k5b] = v0;  MB[LN + k5b] = v1;
    }
}

extern "C" void kernel_launch(void* const* d_in, const int* in_sizes, int n_in,
                              void* d_out, int out_size) {
    const float* E = (const float*)d_in[0];   // emissions   [B, C, L] f32
    const float* T = (const float*)d_in[1];   // transitions [L, L, C, C] f32
    float* M = (float*)d_out;                 // messages    [B, C, L] f32

    dim3 grid(64, 4);                         // 64 subtrees x 4 groups of 8x2 batches
    k_all<<<grid, 256>>>(E, T, M);
}